// round 16
// baseline (speedup 1.0000x reference)
#include <cuda_runtime.h>

#define N_ROWS 1024
#define T_LEN  2048
#define E_NUM  16384
#define K_TAPS 32
#define TPB    128
#define TOUT   16             // outputs per thread (t0 = 16*tid)
#define MAX_B  96             // max experts per dst bucket
#define NF4    520            // f4 slots per row buffer: 8 halo + 512 row
#define GRID   888            // 148 SMs x 6 resident blocks

__device__ int g_ctr;                       // work-steal cursor
__device__ int g_cnt[N_ROWS];               // experts per dst row (zero-init; conv re-zeros)
__device__ int g_lst[N_ROWS][MAX_B];        // expert ids (unordered; conv rank-sorts)

// Swizzle on float4 index: conflict-free for lane-stride-1 fills and
// lane-stride-4 window loads (bijection, all-distinct bank groups).
__device__ __forceinline__ int sw(int f4) { return f4 ^ ((f4 >> 2) & 7); }

__device__ __forceinline__ float f4c(const float4& v, int d) {
    return d == 0 ? v.x : d == 1 ? v.y : d == 2 ? v.z : v.w;  // d compile-time
}

__device__ __forceinline__ void cp16(void* s, const void* g) {
    unsigned sa = (unsigned)__cvta_generic_to_shared(s);
    asm volatile("cp.async.cg.shared.global [%0], [%1], 16;" :: "r"(sa), "l"(g));
}
__device__ __forceinline__ void cp4(void* s, const void* g) {
    unsigned sa = (unsigned)__cvta_generic_to_shared(s);
    asm volatile("cp.async.ca.shared.global [%0], [%1], 4;" :: "r"(sa), "l"(g));
}
#define CP_COMMIT()  asm volatile("cp.async.commit_group;")
#define CP_WAIT1()   asm volatile("cp.async.wait_group 1;")
#define CP_WAIT0()   asm volatile("cp.async.wait_group 0;")

// ---------------------------------------------------------------------------
// Kernel 1: O(E) scatter (order nondeterministic; conv rank-sorts). Resets
// the work-steal cursor. g_cnt==0 on entry (module-load zero-init; conv
// re-zeros each row after consuming it, so graph replays see zeros again).
// ---------------------------------------------------------------------------
__global__ __launch_bounds__(256)
void scatter_experts(const int* __restrict__ dst) {
    int e = blockIdx.x * 256 + threadIdx.x;
    if (e == 0) g_ctr = 0;
    if (e < E_NUM) {
        int v = dst[e];
        int pos = atomicAdd(&g_cnt[v], 1);
        if (pos < MAX_B) g_lst[v][pos] = e;
    }
}

// ---------------------------------------------------------------------------
// Kernel 2: persistent conv blocks, 6/SM. Per row: metadata from smem
// (prefetched by previous row via cp.async attached to an expert group) or
// direct LDG; rank-by-counting deterministic sort; early work-steal claim;
// 3-stage cp.async ring of expert rows, 1 barrier per expert, weight-shift
// register FMAs; epilogue out = x[n] + acc.
// ---------------------------------------------------------------------------
__global__ __launch_bounds__(TPB, 6)
void conv_route_kernel(const float* __restrict__ x,
                       const float* __restrict__ w,
                       const int*   __restrict__ src,
                       float*       __restrict__ out) {
    __shared__ __align__(128) float4 xsb[3][NF4];   // swizzled; [0..7] = halo
    __shared__ __align__(16)  float  wshb[3][K_TAPS];
    __shared__ __align__(16)  int slst[MAX_B];       // unordered list (cp.async target)
    __shared__ int sord[MAX_B];                      // rank-ordered (ascending e)
    __shared__ int snext_cnt;                        // prefetched next-row count
    __shared__ int sh_next;

    const int tid = threadIdx.x;

    if (tid < 8) {                                   // halo, never overwritten
#pragma unroll
        for (int b = 0; b < 3; ++b)
            xsb[b][tid] = make_float4(0.f, 0.f, 0.f, 0.f);
    }

    int offs[12];
#pragma unroll
    for (int c = 0; c < 12; ++c) offs[c] = sw(4 * tid + c);
    const int so0 = sw(8 + tid),       so1 = sw(8 + tid + 128);
    const int so2 = sw(8 + tid + 256), so3 = sw(8 + tid + 384);

#define ISSUE(EIDX, B)                                                         \
    {                                                                          \
        int e = sord[EIDX];                                                    \
        const float* r = x + (size_t)src[e] * T_LEN;                           \
        cp16(&xsb[B][so0], r + 4 * tid);                                       \
        cp16(&xsb[B][so1], r + 4 * (tid + 128));                               \
        cp16(&xsb[B][so2], r + 4 * (tid + 256));                               \
        cp16(&xsb[B][so3], r + 4 * (tid + 384));                               \
        if (tid < 8) cp16(&wshb[B][4 * tid], w + e * K_TAPS + 4 * tid);        \
        CP_COMMIT();                                                           \
    }

#define COMPUTE(B)                                                             \
    {                                                                          \
        const float4* xr = xsb[B];                                             \
        const float4* w4 = (const float4*)wshb[B];                             \
        float wf[K_TAPS];                                                      \
        _Pragma("unroll")                                                      \
        for (int q = 0; q < 8; ++q) {                                          \
            float4 wv = w4[q];                                                 \
            wf[4 * q] = wv.x; wf[4 * q + 1] = wv.y;                            \
            wf[4 * q + 2] = wv.z; wf[4 * q + 3] = wv.w;                        \
        }                                                                      \
        _Pragma("unroll")                                                      \
        for (int c = 0; c < 12; ++c) {                                         \
            float4 V = xr[offs[c]];                                            \
            _Pragma("unroll")                                                  \
            for (int d = 0; d < 4; ++d) {                                      \
                const int u  = 4 * c + d;                                      \
                const float xv = f4c(V, d);                                    \
                const int jlo = (u > 32) ? (u - 32) : 0;                       \
                const int jhi = (u - 1 < 15) ? (u - 1) : 15;                   \
                _Pragma("unroll")                                              \
                for (int j = jlo; j <= jhi; ++j)                               \
                    acc[j] += xv * wf[32 + j - u];                             \
            }                                                                  \
        }                                                                      \
    }

    // Last expert: a lone pending cp.async group is NOT completed by
    // wait_group 1 -> use wait_group 0. On the FIRST step (i==0), attach the
    // next row's metadata prefetch (cnt + raw list) to ISSUE(2)'s group:
    // slst is dead after the sort, so it doubles as the prefetch target.
#define STEP(B)                                                                \
    {                                                                          \
        if (i + 1 < cnt) { CP_WAIT1(); } else { CP_WAIT0(); }                  \
        __syncthreads();                                                       \
        if (i + 2 < cnt) {                                                     \
            if (i == 0 && do_pref) {                                           \
                int nxt = sh_next;                                             \
                if (tid < 24) cp16(&slst[4 * tid], &g_lst[nxt][4 * tid]);      \
                if (tid == 24) cp4(&snext_cnt, &g_cnt[nxt]);                   \
            }                                                                  \
            ISSUE(i + 2, (B + 2) % 3)                                          \
        }                                                                      \
        COMPUTE(B)                                                             \
    }

    int row  = blockIdx.x;
    int pref = 0;                                    // metadata for this row staged?
    while (row < N_ROWS) {
        const int n = row;

        int cnt = pref ? snext_cnt : g_cnt[n];
        if (cnt > MAX_B) cnt = MAX_B;
        if (!pref && tid < cnt) slst[tid] = g_lst[n][tid];
        if (tid == 0) {
            g_cnt[n] = 0;                            // reset for next replay
            sh_next  = GRID + atomicAdd(&g_ctr, 1);  // early claim (latency hidden)
        }
        __syncthreads();                             // slst + sh_next visible

        // Deterministic order: rank-by-counting (ids distinct -> bijection).
        if (tid < cnt) {
            int key  = slst[tid];
            int rank = 0;
            for (int j = 0; j < cnt; ++j) rank += (slst[j] < key);
            sord[rank] = key;
        }
        __syncthreads();                             // sord ready; slst now dead

        const int nxt     = sh_next;
        const int do_pref = (cnt >= 3) && (nxt < N_ROWS);

        float acc[TOUT];
#pragma unroll
        for (int j = 0; j < TOUT; ++j) acc[j] = 0.0f;

        if (cnt > 0) ISSUE(0, 0)
        if (cnt > 1) ISSUE(1, 1)

        int i = 0;
        while (i < cnt) {
            STEP(0) ++i; if (i >= cnt) break;
            STEP(1) ++i; if (i >= cnt) break;
            STEP(2) ++i;
        }

        // Epilogue: out[n] = x[n] + acc
        const float4* xrow = (const float4*)(x + (size_t)n * T_LEN);
        float4*       orow = (float4*)(out + (size_t)n * T_LEN);
#pragma unroll
        for (int p2 = 0; p2 < 4; ++p2) {
            float4 a = xrow[4 * tid + p2];
            a.x += acc[4 * p2 + 0];
            a.y += acc[4 * p2 + 1];
            a.z += acc[4 * p2 + 2];
            a.w += acc[4 * p2 + 3];
            orow[4 * tid + p2] = a;
        }

        row  = nxt;
        pref = do_pref;
        __syncthreads();   // all reads of slst/snext_cnt/sh_next done before reuse
    }
#undef STEP
#undef COMPUTE
#undef ISSUE
}

// ---------------------------------------------------------------------------
extern "C" void kernel_launch(void* const* d_in, const int* in_sizes, int n_in,
                              void* d_out, int out_size) {
    const float* x   = (const float*)d_in[0];
    const float* w   = (const float*)d_in[1];
    const int*   src = (const int*)d_in[2];
    const int*   dst = (const int*)d_in[3];
    float*       out = (float*)d_out;

    scatter_experts<<<E_NUM / 256, 256>>>(dst);
    conv_route_kernel<<<GRID, TPB>>>(x, w, src, out);
}